// round 15
// baseline (speedup 1.0000x reference)
#include <cuda_runtime.h>
#include <cuda_fp16.h>
#include <math.h>
#include <stdint.h>

// Gaussian KDE log-likelihood via warp-level fp16 mma.sync + direct biased
// 2^v accumulation. 2048 CTAs (64 mtiles x 32 n-slices), 2 CTAs/SM,
// 3-stage cp.async pipeline; final logsumexp combine FUSED into the main
// kernel (last CTA per mtile combines). Baseline PTX only (compute_103-safe).

#define D      64
#define ZCONST 58.812066125099045f
#define LOG2E  1.4426950408889634f
#define LN2F   0.6931471805599453f
#define QBIAS  64.0f

#define M_ROWS 8192
#define N_ROWS 16384
#define MT     128
#define NT     128
#define NSLICES 32
#define SLICE_N 512
#define TILES_PER 4          // SLICE_N / NT

// ---------------- device scratch ----------------
__device__ __half g_A16[M_ROWS * D];   // test * log2e
__device__ __half g_B16[N_ROWS * D];   // train
__device__ float g_cm[M_ROWS];
__device__ float g_q2[N_ROWS];         // (ln w - 0.5||y||^2)*log2e + QBIAS
__device__ float g_logW;
__device__ float g_psum[NSLICES * M_ROWS];   // [slice][row]
__device__ int   g_done[M_ROWS / MT];        // per-mtile arrival counters

// ---------------- helpers ----------------
__device__ __forceinline__ uint32_t smem_u32(const void* p) {
    uint32_t a;
    asm("{ .reg .u64 t; cvta.to.shared.u64 t, %1; cvt.u32.u64 %0, t; }" : "=r"(a) : "l"(p));
    return a;
}
__device__ __forceinline__ float ex2f(float x) {
    float r; asm("ex2.approx.f32 %0, %1;" : "=f"(r) : "f"(x)); return r;
}
// packed f32x2 -> f16x2
__device__ __forceinline__ uint32_t f2h2(float lo, float hi) {
    uint32_t r;
    asm("cvt.rn.f16x2.f32 %0, %1, %2;" : "=r"(r) : "f"(hi), "f"(lo));
    return r;
}
__device__ __forceinline__ void cpa16(uint32_t dst, const void* src) {
    asm volatile("cp.async.cg.shared.global [%0], [%1], 16;" :: "r"(dst), "l"(src));
}
__device__ __forceinline__ void ldsm4(uint32_t& r0, uint32_t& r1, uint32_t& r2,
                                      uint32_t& r3, uint32_t addr) {
    asm volatile("ldmatrix.sync.aligned.m8n8.x4.shared.b16 {%0,%1,%2,%3}, [%4];"
                 : "=r"(r0), "=r"(r1), "=r"(r2), "=r"(r3) : "r"(addr));
}
__device__ __forceinline__ void mma16816(float* c, const uint32_t* a,
                                         uint32_t b0, uint32_t b1) {
    asm volatile("mma.sync.aligned.m16n8k16.row.col.f32.f16.f16.f32 "
                 "{%0,%1,%2,%3}, {%4,%5,%6,%7}, {%8,%9}, {%0,%1,%2,%3};"
                 : "+f"(c[0]), "+f"(c[1]), "+f"(c[2]), "+f"(c[3])
                 : "r"(a[0]), "r"(a[1]), "r"(a[2]), "r"(a[3]), "r"(b0), "r"(b1));
}
#define SWZ(o) ((o) ^ (((o) >> 3) & 0x70))

// ---------------- pre-kernel (conversion + norms + wsum + counter reset) ----------------
__global__ void kde_pre(const float* __restrict__ testX,
                        const float* __restrict__ trainX,
                        const float* __restrict__ w) {
    if (blockIdx.x == gridDim.x - 1) {
        // reset per-mtile counters for this replay
        if (threadIdx.x < M_ROWS / MT) g_done[threadIdx.x] = 0;
        __shared__ float red[256];
        float s = 0.f;
        for (int j = threadIdx.x; j < N_ROWS; j += 256) s += w[j];
        red[threadIdx.x] = s;
        __syncthreads();
#pragma unroll
        for (int o = 128; o > 0; o >>= 1) {
            if (threadIdx.x < o) red[threadIdx.x] += red[threadIdx.x + o];
            __syncthreads();
        }
        if (threadIdx.x == 0) g_logW = logf(red[0]);
        return;
    }

    int gt = blockIdx.x * blockDim.x + threadIdx.x;
    int row = gt >> 3;
    int part = gt & 7;
    bool is_test = row < M_ROWS;
    int r = is_test ? row : row - M_ROWS;
    if (!is_test && r >= N_ROWS) return;

    const float* src = (is_test ? testX : trainX) + (size_t)r * D + part * 8;
    float4 v0 = *(const float4*)src;
    float4 v1 = *(const float4*)(src + 4);
    float s = v0.x * v0.x + v0.y * v0.y + v0.z * v0.z + v0.w * v0.w
            + v1.x * v1.x + v1.y * v1.y + v1.z * v1.z + v1.w * v1.w;
    s += __shfl_xor_sync(0xffffffffu, s, 1);
    s += __shfl_xor_sync(0xffffffffu, s, 2);
    s += __shfl_xor_sync(0xffffffffu, s, 4);

    const float scale = is_test ? LOG2E : 1.0f;
    uint4 h;
    h.x = f2h2(v0.x * scale, v0.y * scale);
    h.y = f2h2(v0.z * scale, v0.w * scale);
    h.z = f2h2(v1.x * scale, v1.y * scale);
    h.w = f2h2(v1.z * scale, v1.w * scale);
    char* dst = (char*)(is_test ? g_A16 : g_B16) + (size_t)r * 128 + part * 16;
    *(uint4*)dst = h;

    if (part == 0) {
        if (is_test) g_cm[r] = -0.5f * s - ZCONST;
        else         g_q2[r] = (logf(fmaxf(w[r], 1e-37f)) - 0.5f * s) * LOG2E + QBIAS;
    }
}

// ---------------- main kernel (+ fused final combine) ----------------
// dyn smem: [0, 2KB) q2 slice ; [2KB, 50KB) B tiles: 3 bufs of 16KB
#define OB 2048
#define SMEM_BYTES (2048 + 3 * 16384)   // 51200

__global__ __launch_bounds__(256, 2) void kde_main(float* __restrict__ out) {
    extern __shared__ char sm[];
    float* sQ = (float*)sm;
    const uint32_t smb = smem_u32(sm);

    const int tid  = threadIdx.x;
    const int wid  = tid >> 5;
    const int lane = tid & 31;
    const int g    = lane >> 2;
    const int tc   = lane & 3;
    const int mtile = blockIdx.x >> 5;
    const int slice = blockIdx.x & 31;
    const int m0 = mtile * MT;
    const int nbase = slice * SLICE_N;

    // B tile loader: 2 threads per row, 4 x 16B chunks each
    const int rld = tid >> 1;
    const int cb  = (tid & 1) * 4;

#define PREFETCH(tt) do {                                                          \
    const char* _src = (const char*)(g_B16 + (size_t)(nbase + (tt) * NT + rld) * D) + cb * 16; \
    uint32_t _dst = smb + OB + ((tt) % 3) * 16384;                                 \
    _Pragma("unroll")                                                              \
    for (int c = 0; c < 4; c++) {                                                  \
        uint32_t off = rld * 128 + (cb + c) * 16;                                  \
        cpa16(_dst + SWZ(off), _src + c * 16);                                     \
    }                                                                              \
    asm volatile("cp.async.commit_group;" ::: "memory");                           \
} while (0)

    // depth-2 prefetch
    PREFETCH(0);
    PREFETCH(1);

    // hoisted A-fragment loads (overlap cp.async)
    uint32_t A[4][4];
    {
        size_t base = (size_t)(m0 + wid * 16 + g) * D + 2 * tc;
#pragma unroll
        for (int ks = 0; ks < 4; ks++) {
            size_t o = base + ks * 16;
            A[ks][0] = *(const uint32_t*)(g_A16 + o);
            A[ks][1] = *(const uint32_t*)(g_A16 + o + 8 * D);
            A[ks][2] = *(const uint32_t*)(g_A16 + o + 8);
            A[ks][3] = *(const uint32_t*)(g_A16 + o + 8 * D + 8);
        }
    }

    // preload q2 slice into smem (512 floats)
    if (tid < SLICE_N / 4)
        ((float4*)sQ)[tid] = ((const float4*)(g_q2 + nbase))[tid];

    const uint32_t lm_off0 = SWZ((uint32_t)((lane & 7) * 128 + (lane >> 3) * 16));
    const uint32_t lm_off1 = SWZ((uint32_t)((lane & 7) * 128 + 64 + (lane >> 3) * 16));

    float s0a = 0.f, s0b = 0.f, s1a = 0.f, s1b = 0.f;
    float C0[4][4], C1[4][4];
    uint32_t b[4][8];

#define CHUNK_MMA(CB, ng, bB) do {                                                 \
    _Pragma("unroll")                                                              \
    for (int j = 0; j < 4; j++) {                                                  \
        uint32_t nb = ((ng) * 4 + j) * 1024;                                       \
        ldsm4(b[j][0], b[j][1], b[j][2], b[j][3], (bB) + nb + lm_off0);            \
        ldsm4(b[j][4], b[j][5], b[j][6], b[j][7], (bB) + nb + lm_off1);            \
    }                                                                              \
    _Pragma("unroll")                                                              \
    for (int j = 0; j < 4; j++) {                                                  \
        (CB)[j][0] = 0.f; (CB)[j][1] = 0.f; (CB)[j][2] = 0.f; (CB)[j][3] = 0.f;    \
    }                                                                              \
    _Pragma("unroll")                                                              \
    for (int ks = 0; ks < 4; ks++)                                                 \
        _Pragma("unroll")                                                          \
        for (int j = 0; j < 4; j++)                                                \
            mma16816((CB)[j], A[ks], b[j][2 * ks], b[j][2 * ks + 1]);              \
} while (0)

#define CHUNK_EPI(CB, ng, t) do {                                                  \
    _Pragma("unroll")                                                              \
    for (int j = 0; j < 4; j++) {                                                  \
        int ns = (ng) * 4 + j;                                                     \
        float2 q = *(const float2*)(sQ + (t) * NT + ns * 8 + 2 * tc);              \
        float v0 = (CB)[j][0] + q.x, v1 = (CB)[j][1] + q.y;                        \
        float v2 = (CB)[j][2] + q.x, v3 = (CB)[j][3] + q.y;                        \
        if (j & 1) { s0b += ex2f(v0) + ex2f(v1); s1b += ex2f(v2) + ex2f(v3); }     \
        else       { s0a += ex2f(v0) + ex2f(v1); s1a += ex2f(v2) + ex2f(v3); }     \
    }                                                                              \
} while (0)

#define TILE_BODY(t) do {                                                          \
    if ((t) + 1 < TILES_PER)                                                       \
        asm volatile("cp.async.wait_group 1;" ::: "memory");                       \
    else                                                                           \
        asm volatile("cp.async.wait_group 0;" ::: "memory");                       \
    __syncthreads();                                                               \
    if ((t) + 2 < TILES_PER) PREFETCH((t) + 2);                                    \
    const uint32_t bB = smb + OB + ((t) % 3) * 16384;                              \
    CHUNK_MMA(C0, 0, bB);                                                          \
    CHUNK_MMA(C1, 1, bB);  CHUNK_EPI(C0, 0, t);                                    \
    CHUNK_MMA(C0, 2, bB);  CHUNK_EPI(C1, 1, t);                                    \
    CHUNK_MMA(C1, 3, bB);  CHUNK_EPI(C0, 2, t);                                    \
    CHUNK_EPI(C1, 3, t);                                                           \
} while (0)

    { TILE_BODY(0); }
    { TILE_BODY(1); }
    { TILE_BODY(2); }
    { TILE_BODY(3); }

    float vsum0 = (s0a + s0b);
    float vsum1 = (s1a + s1b);

    // combine 4 lanes (tc = 0..3) holding the same rows
#pragma unroll
    for (int off = 1; off <= 2; off <<= 1) {
        vsum0 += __shfl_xor_sync(0xffffffffu, vsum0, off);
        vsum1 += __shfl_xor_sync(0xffffffffu, vsum1, off);
    }

    if (tc == 0) {
        int r0 = m0 + wid * 16 + g;
        g_psum[(size_t)slice * M_ROWS + r0] = vsum0;
        g_psum[(size_t)slice * M_ROWS + r0 + 8] = vsum1;
    }

    // ---- fused final combine: last CTA of this mtile sums all 32 slices ----
    __syncthreads();
    __shared__ int s_old;
    if (tid == 0) {
        __threadfence();                       // publish psum stores of this CTA
        s_old = atomicAdd(&g_done[mtile], 1);
    }
    __syncthreads();
    if (s_old == NSLICES - 1) {
        if (tid == 0) __threadfence();         // acquire: all 32 CTAs' psum visible
        __syncthreads();
        if (tid < MT) {
            int r = m0 + tid;                  // coalesced across tid per slice
            float p0 = 0.f, p1 = 0.f, p2 = 0.f, p3 = 0.f;
#pragma unroll
            for (int i = 0; i < NSLICES; i += 4) {
                p0 += g_psum[(size_t)(i + 0) * M_ROWS + r];
                p1 += g_psum[(size_t)(i + 1) * M_ROWS + r];
                p2 += g_psum[(size_t)(i + 2) * M_ROWS + r];
                p3 += g_psum[(size_t)(i + 3) * M_ROWS + r];
            }
            float s = (p0 + p1) + (p2 + p3);
            out[r] = g_cm[r] + logf(s) - QBIAS * LN2F - g_logW;
        }
    }
}

// ---------------------------------------------------------------------------
extern "C" void kernel_launch(void* const* d_in, const int* in_sizes, int n_in,
                              void* d_out, int out_size) {
    const float* testX  = (const float*)d_in[0];
    const float* trainX = (const float*)d_in[1];
    const float* w      = (const float*)d_in[2];
    float* out = (float*)d_out;

    static int smem_set = 0;
    if (!smem_set) {
        cudaFuncSetAttribute(kde_main, cudaFuncAttributeMaxDynamicSharedMemorySize, SMEM_BYTES);
        smem_set = 1;
    }

    kde_pre<<<((M_ROWS + N_ROWS) * 8) / 256 + 1, 256>>>(testX, trainX, w);
    kde_main<<<M_ROWS / MT * NSLICES, 256, SMEM_BYTES>>>(out);
}

// round 16
// speedup vs baseline: 1.1309x; 1.1309x over previous
#include <cuda_runtime.h>
#include <cuda_fp16.h>
#include <math.h>
#include <stdint.h>

// Gaussian KDE log-likelihood via warp-level fp16 mma.sync + direct biased
// 2^v accumulation. 2048 CTAs (64 mtiles x 32 n-slices), 2 CTAs/SM,
// 3-stage cp.async pipeline. Warp tile 32x64 (halved LDSM redundancy).
// Baseline PTX only (compute_103-safe).

#define D      64
#define ZCONST 58.812066125099045f
#define LOG2E  1.4426950408889634f
#define LN2F   0.6931471805599453f
#define QBIAS  64.0f

#define M_ROWS 8192
#define N_ROWS 16384
#define MT     128
#define NT     128
#define NSLICES 32
#define SLICE_N 512
#define TILES_PER 4          // SLICE_N / NT

// ---------------- device scratch ----------------
__device__ __half g_A16[M_ROWS * D];   // test * log2e
__device__ __half g_B16[N_ROWS * D];   // train
__device__ float g_cm[M_ROWS];
__device__ float g_q2[N_ROWS];         // (ln w - 0.5||y||^2)*log2e + QBIAS
__device__ float g_logW;
__device__ float g_psum[NSLICES * M_ROWS];   // [slice][row]

// ---------------- helpers ----------------
__device__ __forceinline__ uint32_t smem_u32(const void* p) {
    uint32_t a;
    asm("{ .reg .u64 t; cvta.to.shared.u64 t, %1; cvt.u32.u64 %0, t; }" : "=r"(a) : "l"(p));
    return a;
}
__device__ __forceinline__ float ex2f(float x) {
    float r; asm("ex2.approx.f32 %0, %1;" : "=f"(r) : "f"(x)); return r;
}
__device__ __forceinline__ uint32_t f2h2(float lo, float hi) {
    uint32_t r;
    asm("cvt.rn.f16x2.f32 %0, %1, %2;" : "=r"(r) : "f"(hi), "f"(lo));
    return r;
}
__device__ __forceinline__ void cpa16(uint32_t dst, const void* src) {
    asm volatile("cp.async.cg.shared.global [%0], [%1], 16;" :: "r"(dst), "l"(src));
}
__device__ __forceinline__ void ldsm4(uint32_t& r0, uint32_t& r1, uint32_t& r2,
                                      uint32_t& r3, uint32_t addr) {
    asm volatile("ldmatrix.sync.aligned.m8n8.x4.shared.b16 {%0,%1,%2,%3}, [%4];"
                 : "=r"(r0), "=r"(r1), "=r"(r2), "=r"(r3) : "r"(addr));
}
__device__ __forceinline__ void mma16816(float* c, const uint32_t* a,
                                         uint32_t b0, uint32_t b1) {
    asm volatile("mma.sync.aligned.m16n8k16.row.col.f32.f16.f16.f32 "
                 "{%0,%1,%2,%3}, {%4,%5,%6,%7}, {%8,%9}, {%0,%1,%2,%3};"
                 : "+f"(c[0]), "+f"(c[1]), "+f"(c[2]), "+f"(c[3])
                 : "r"(a[0]), "r"(a[1]), "r"(a[2]), "r"(a[3]), "r"(b0), "r"(b1));
}
#define SWZ(o) ((o) ^ (((o) >> 3) & 0x70))

// ---------------- pre-kernel (conversion + norms + wsum) ----------------
__global__ void kde_pre(const float* __restrict__ testX,
                        const float* __restrict__ trainX,
                        const float* __restrict__ w) {
    if (blockIdx.x == gridDim.x - 1) {
        __shared__ float red[256];
        float s = 0.f;
        for (int j = threadIdx.x; j < N_ROWS; j += 256) s += w[j];
        red[threadIdx.x] = s;
        __syncthreads();
#pragma unroll
        for (int o = 128; o > 0; o >>= 1) {
            if (threadIdx.x < o) red[threadIdx.x] += red[threadIdx.x + o];
            __syncthreads();
        }
        if (threadIdx.x == 0) g_logW = logf(red[0]);
        return;
    }

    int gt = blockIdx.x * blockDim.x + threadIdx.x;
    int row = gt >> 3;
    int part = gt & 7;
    bool is_test = row < M_ROWS;
    int r = is_test ? row : row - M_ROWS;
    if (!is_test && r >= N_ROWS) return;

    const float* src = (is_test ? testX : trainX) + (size_t)r * D + part * 8;
    float4 v0 = *(const float4*)src;
    float4 v1 = *(const float4*)(src + 4);
    float s = v0.x * v0.x + v0.y * v0.y + v0.z * v0.z + v0.w * v0.w
            + v1.x * v1.x + v1.y * v1.y + v1.z * v1.z + v1.w * v1.w;
    s += __shfl_xor_sync(0xffffffffu, s, 1);
    s += __shfl_xor_sync(0xffffffffu, s, 2);
    s += __shfl_xor_sync(0xffffffffu, s, 4);

    const float scale = is_test ? LOG2E : 1.0f;
    uint4 h;
    h.x = f2h2(v0.x * scale, v0.y * scale);
    h.y = f2h2(v0.z * scale, v0.w * scale);
    h.z = f2h2(v1.x * scale, v1.y * scale);
    h.w = f2h2(v1.z * scale, v1.w * scale);
    char* dst = (char*)(is_test ? g_A16 : g_B16) + (size_t)r * 128 + part * 16;
    *(uint4*)dst = h;

    if (part == 0) {
        if (is_test) g_cm[r] = -0.5f * s - ZCONST;
        else         g_q2[r] = (logf(fmaxf(w[r], 1e-37f)) - 0.5f * s) * LOG2E + QBIAS;
    }
}

// ---------------- main kernel ----------------
// dyn smem: [0, 2KB) q2 slice ; [2KB, 50KB) B tiles: 3 bufs of 16KB
#define OB 2048
#define SMEM_BYTES (2048 + 3 * 16384)   // 51200

__global__ __launch_bounds__(256, 2) void kde_main() {
    extern __shared__ char sm[];
    float* sQ = (float*)sm;
    const uint32_t smb = smem_u32(sm);

    const int tid  = threadIdx.x;
    const int wid  = tid >> 5;
    const int lane = tid & 31;
    const int g    = lane >> 2;
    const int tc   = lane & 3;
    const int mb   = wid >> 1;          // M row-block 0..3 (32 rows each)
    const int ch   = wid & 1;           // N col-half 0..1 (64 cols each)
    const int mtile = blockIdx.x >> 5;
    const int slice = blockIdx.x & 31;
    const int m0 = mtile * MT;
    const int nbase = slice * SLICE_N;

    // B tile loader: 2 threads per row, 4 x 16B chunks each
    const int rld = tid >> 1;
    const int cb  = (tid & 1) * 4;

#define PREFETCH(tt) do {                                                          \
    const char* _src = (const char*)(g_B16 + (size_t)(nbase + (tt) * NT + rld) * D) + cb * 16; \
    uint32_t _dst = smb + OB + ((tt) % 3) * 16384;                                 \
    _Pragma("unroll")                                                              \
    for (int c = 0; c < 4; c++) {                                                  \
        uint32_t off = rld * 128 + (cb + c) * 16;                                  \
        cpa16(_dst + SWZ(off), _src + c * 16);                                     \
    }                                                                              \
    asm volatile("cp.async.commit_group;" ::: "memory");                           \
} while (0)

    PREFETCH(0);
    PREFETCH(1);

    // A fragments: 32 rows = two m16 blocks, rows m0 + mb*32 + {0..15, 16..31}
    uint32_t A0[4][4], A1[4][4];
    {
        size_t base = (size_t)(m0 + mb * 32 + g) * D + 2 * tc;
#pragma unroll
        for (int ks = 0; ks < 4; ks++) {
            size_t o = base + ks * 16;
            A0[ks][0] = *(const uint32_t*)(g_A16 + o);
            A0[ks][1] = *(const uint32_t*)(g_A16 + o + 8 * D);
            A0[ks][2] = *(const uint32_t*)(g_A16 + o + 8);
            A0[ks][3] = *(const uint32_t*)(g_A16 + o + 8 * D + 8);
            size_t o1 = o + 16 * D;
            A1[ks][0] = *(const uint32_t*)(g_A16 + o1);
            A1[ks][1] = *(const uint32_t*)(g_A16 + o1 + 8 * D);
            A1[ks][2] = *(const uint32_t*)(g_A16 + o1 + 8);
            A1[ks][3] = *(const uint32_t*)(g_A16 + o1 + 8 * D + 8);
        }
    }

    // preload q2 slice into smem (512 floats)
    if (tid < SLICE_N / 4)
        ((float4*)sQ)[tid] = ((const float4*)(g_q2 + nbase))[tid];

    const uint32_t lm_off0 = SWZ((uint32_t)((lane & 7) * 128 + (lane >> 3) * 16));
    const uint32_t lm_off1 = SWZ((uint32_t)((lane & 7) * 128 + 64 + (lane >> 3) * 16));
    const uint32_t nsbase = ch * 8 * 1024;   // this warp's col-half in the B tile

    // 4 row sums per thread: rows g, g+8 (block0), g+16, g+24 (block1)
    float vs0 = 0.f, vs1 = 0.f, vs2 = 0.f, vs3 = 0.f;
    // chunk = 2 ns; C buffer: [j][blk*4 + i]
    float C0[2][8], C1[2][8];
    uint32_t b[2][8];

#define CHUNK_MMA(CB, c, bB) do {                                                  \
    _Pragma("unroll")                                                              \
    for (int j = 0; j < 2; j++) {                                                  \
        uint32_t nb = nsbase + ((c) * 2 + j) * 1024;                               \
        ldsm4(b[j][0], b[j][1], b[j][2], b[j][3], (bB) + nb + lm_off0);            \
        ldsm4(b[j][4], b[j][5], b[j][6], b[j][7], (bB) + nb + lm_off1);            \
    }                                                                              \
    _Pragma("unroll")                                                              \
    for (int j = 0; j < 2; j++)                                                    \
        _Pragma("unroll")                                                          \
        for (int i = 0; i < 8; i++) (CB)[j][i] = 0.f;                              \
    _Pragma("unroll")                                                              \
    for (int ks = 0; ks < 4; ks++)                                                 \
        _Pragma("unroll")                                                          \
        for (int j = 0; j < 2; j++) {                                              \
            mma16816((CB)[j],     A0[ks], b[j][2 * ks], b[j][2 * ks + 1]);         \
            mma16816((CB)[j] + 4, A1[ks], b[j][2 * ks], b[j][2 * ks + 1]);         \
        }                                                                          \
} while (0)

#define CHUNK_EPI(CB, c, t) do {                                                   \
    _Pragma("unroll")                                                              \
    for (int j = 0; j < 2; j++) {                                                  \
        int nc = ch * 64 + ((c) * 2 + j) * 8 + 2 * tc;                             \
        float2 q = *(const float2*)(sQ + (t) * NT + nc);                           \
        vs0 += ex2f((CB)[j][0] + q.x) + ex2f((CB)[j][1] + q.y);                    \
        vs1 += ex2f((CB)[j][2] + q.x) + ex2f((CB)[j][3] + q.y);                    \
        vs2 += ex2f((CB)[j][4] + q.x) + ex2f((CB)[j][5] + q.y);                    \
        vs3 += ex2f((CB)[j][6] + q.x) + ex2f((CB)[j][7] + q.y);                    \
    }                                                                              \
} while (0)

#define TILE_BODY(t) do {                                                          \
    if ((t) + 1 < TILES_PER)                                                       \
        asm volatile("cp.async.wait_group 1;" ::: "memory");                       \
    else                                                                           \
        asm volatile("cp.async.wait_group 0;" ::: "memory");                       \
    __syncthreads();                                                               \
    if ((t) + 2 < TILES_PER) PREFETCH((t) + 2);                                    \
    const uint32_t bB = smb + OB + ((t) % 3) * 16384;                              \
    CHUNK_MMA(C0, 0, bB);                                                          \
    CHUNK_MMA(C1, 1, bB);  CHUNK_EPI(C0, 0, t);                                    \
    CHUNK_MMA(C0, 2, bB);  CHUNK_EPI(C1, 1, t);                                    \
    CHUNK_MMA(C1, 3, bB);  CHUNK_EPI(C0, 2, t);                                    \
    CHUNK_EPI(C1, 3, t);                                                           \
} while (0)

    { TILE_BODY(0); }
    { TILE_BODY(1); }
    { TILE_BODY(2); }
    { TILE_BODY(3); }

    // combine 4 tc-lanes (same rows, different cols)
#pragma unroll
    for (int off = 1; off <= 2; off <<= 1) {
        vs0 += __shfl_xor_sync(0xffffffffu, vs0, off);
        vs1 += __shfl_xor_sync(0xffffffffu, vs1, off);
        vs2 += __shfl_xor_sync(0xffffffffu, vs2, off);
        vs3 += __shfl_xor_sync(0xffffffffu, vs3, off);
    }

    // cross-warp combine: ch=1 deposits, ch=0 adds and writes psum
    float* sRed = (float*)sm;   // reuse sQ area (all reads of sQ are done)
    __syncthreads();
    if (ch == 1 && tc == 0) {
        int rl = mb * 32 + g;
        sRed[rl]      = vs0;
        sRed[rl + 8]  = vs1;
        sRed[rl + 16] = vs2;
        sRed[rl + 24] = vs3;
    }
    __syncthreads();
    if (ch == 0 && tc == 0) {
        int rl = mb * 32 + g;
        int r0 = m0 + rl;
        g_psum[(size_t)slice * M_ROWS + r0]      = vs0 + sRed[rl];
        g_psum[(size_t)slice * M_ROWS + r0 + 8]  = vs1 + sRed[rl + 8];
        g_psum[(size_t)slice * M_ROWS + r0 + 16] = vs2 + sRed[rl + 16];
        g_psum[(size_t)slice * M_ROWS + r0 + 24] = vs3 + sRed[rl + 24];
    }
}

// ---------------- final combine ([slice][row]: coalesced, MLP 32) ----------------
__global__ void kde_final(float* __restrict__ out) {
    int r = blockIdx.x * blockDim.x + threadIdx.x;
    if (r < M_ROWS) {
        float p0 = 0.f, p1 = 0.f, p2 = 0.f, p3 = 0.f;
#pragma unroll
        for (int i = 0; i < NSLICES; i += 4) {
            p0 += g_psum[(size_t)(i + 0) * M_ROWS + r];
            p1 += g_psum[(size_t)(i + 1) * M_ROWS + r];
            p2 += g_psum[(size_t)(i + 2) * M_ROWS + r];
            p3 += g_psum[(size_t)(i + 3) * M_ROWS + r];
        }
        float s = (p0 + p1) + (p2 + p3);
        out[r] = g_cm[r] + logf(s) - QBIAS * LN2F - g_logW;
    }
}

// ---------------------------------------------------------------------------
extern "C" void kernel_launch(void* const* d_in, const int* in_sizes, int n_in,
                              void* d_out, int out_size) {
    const float* testX  = (const float*)d_in[0];
    const float* trainX = (const float*)d_in[1];
    const float* w      = (const float*)d_in[2];
    float* out = (float*)d_out;

    static int smem_set = 0;
    if (!smem_set) {
        cudaFuncSetAttribute(kde_main, cudaFuncAttributeMaxDynamicSharedMemorySize, SMEM_BYTES);
        smem_set = 1;
    }

    kde_pre<<<((M_ROWS + N_ROWS) * 8) / 256 + 1, 256>>>(testX, trainX, w);
    kde_main<<<M_ROWS / MT * NSLICES, 256, SMEM_BYTES>>>();
    kde_final<<<(M_ROWS + 127) / 128, 128>>>(out);
}